// round 15
// baseline (speedup 1.0000x reference)
#include <cuda_runtime.h>
#include <cuda_bf16.h>
#include <math.h>
#include <cstdint>

#define NTOK 8192
typedef unsigned long long u64;
typedef __nv_bfloat16 bf16;

// ---------------- scratch ----------------
__device__ float g_Qb[NTOK * 128];
__device__ float g_Kb[NTOK * 128];
__device__ float g_Vb[NTOK * 128];
__device__ float g_Rb[NTOK * 128];
__device__ float g_H[NTOK * 256];      // reused as O partials (2 x 1M floats)
__device__ float g_L[2 * NTOK];
__device__ bf16  g_Xh[NTOK * 128];
__device__ bf16  g_Xl[NTOK * 128];
__device__ bf16  g_Wth[13 * 256 * 128];
__device__ bf16  g_Wtl[13 * 256 * 128];

// ---------------- helpers ----------------
__device__ __forceinline__ float gelu_f(float x) {
    return 0.5f * x * (1.0f + erff(x * 0.7071067811865476f));
}
__device__ __forceinline__ uint32_t pack_bf16(float lo, float hi) {
    uint32_t r; asm("cvt.rn.bf16x2.f32 %0, %1, %2;" : "=r"(r) : "f"(hi), "f"(lo)); return r;
}
__device__ __forceinline__ uint16_t pack_e4m3(float lo, float hi) {
    uint16_t r; asm("cvt.rn.satfinite.e4m3x2.f32 %0, %1, %2;" : "=h"(r) : "f"(hi), "f"(lo)); return r;
}
__device__ __forceinline__ uint32_t smem_u32(const void* p) {
    uint32_t a; asm("{ .reg .u64 t; cvta.to.shared.u64 t, %1; cvt.u32.u64 %0, t; }" : "=r"(a) : "l"(p));
    return a;
}
__device__ __forceinline__ void split_bf16(float v, bf16& h, bf16& l) {
    h = __float2bfloat16(v);
    l = __float2bfloat16(v - __bfloat162float(h));
}
__device__ __forceinline__ float ex2(float x) {
    float r; asm("ex2.approx.ftz.f32 %0, %1;" : "=f"(r) : "f"(x)); return r;
}

// ---------------- mma.sync / ldmatrix / cp.async primitives ----------------
__device__ __forceinline__ void mma16816(float* c, const uint32_t* a, uint32_t b0, uint32_t b1) {
    asm volatile("mma.sync.aligned.m16n8k16.row.col.f32.bf16.bf16.f32 "
        "{%0,%1,%2,%3}, {%4,%5,%6,%7}, {%8,%9}, {%0,%1,%2,%3};"
        : "+f"(c[0]), "+f"(c[1]), "+f"(c[2]), "+f"(c[3])
        : "r"(a[0]), "r"(a[1]), "r"(a[2]), "r"(a[3]), "r"(b0), "r"(b1));
}
// fp8 e4m3: m16n8k32, fragment layout byte-identical to bf16 m16n8k16 (b16 = 2 fp8)
__device__ __forceinline__ void mma16832f8(float* c, const uint32_t* a, uint32_t b0, uint32_t b1) {
    asm volatile("mma.sync.aligned.m16n8k32.row.col.f32.e4m3.e4m3.f32 "
        "{%0,%1,%2,%3}, {%4,%5,%6,%7}, {%8,%9}, {%0,%1,%2,%3};"
        : "+f"(c[0]), "+f"(c[1]), "+f"(c[2]), "+f"(c[3])
        : "r"(a[0]), "r"(a[1]), "r"(a[2]), "r"(a[3]), "r"(b0), "r"(b1));
}
__device__ __forceinline__ void ldsm4(uint32_t* r, uint32_t addr) {
    asm volatile("ldmatrix.sync.aligned.m8n8.x4.shared.b16 {%0,%1,%2,%3}, [%4];"
        : "=r"(r[0]), "=r"(r[1]), "=r"(r[2]), "=r"(r[3]) : "r"(addr));
}
__device__ __forceinline__ void cp16(uint32_t sdst, const void* gsrc) {
    asm volatile("cp.async.cg.shared.global [%0], [%1], 16;" :: "r"(sdst), "l"(gsrc));
}
#define CP_COMMIT() asm volatile("cp.async.commit_group;" ::: "memory")
#define CP_WAIT1()  asm volatile("cp.async.wait_group 1;" ::: "memory")
#define CP_WAIT0()  asm volatile("cp.async.wait_group 0;" ::: "memory")

// tile geometry
#define TROW 272                  // 128 bf16 rows padded
#define KROW 144                  // 128 fp8 rows padded
#define TILE_BYTES (128 * TROW)
#define TILE8_BYTES (128 * KROW)

__device__ __forceinline__ void copy_tile_async(char* dst, const bf16* __restrict__ src,
                                                int rstride, int tid) {
    uint32_t d = smem_u32(dst);
#pragma unroll
    for (int rep = 0; rep < 8; rep++) {
        int chunk = rep * 256 + tid;       // 2048 chunks of 16B
        int r = chunk >> 4, c = chunk & 15;
        cp16(d + r * TROW + c * 16, src + (size_t)r * rstride + c * 8);
    }
}
__device__ __forceinline__ void copy_x64_async(char* dst, const bf16* __restrict__ src, int tid) {
    uint32_t d = smem_u32(dst);
#pragma unroll
    for (int rep = 0; rep < 4; rep++) {
        int chunk = rep * 256 + tid;       // 1024 chunks (64 rows)
        int r = chunk >> 4, c = chunk & 15;
        cp16(d + r * TROW + c * 16, src + (size_t)r * 128 + c * 8);
    }
}
// fp8 tile: 128 rows x 128 bytes
__device__ __forceinline__ void copy_tile8_async(char* dst, const uint8_t* __restrict__ src, int tid) {
    uint32_t d = smem_u32(dst);
#pragma unroll
    for (int rep = 0; rep < 4; rep++) {
        int chunk = rep * 256 + tid;       // 1024 chunks: 128 rows x 8
        int r = chunk >> 3, c = chunk & 7;
        cp16(d + r * KROW + c * 16, src + (size_t)r * 128 + c * 16);
    }
}

// ---------------- weight transpose + bf16 split (once per launch) ----------------
struct WPtrs { const float* w[13]; int cols[13]; };

__global__ void __launch_bounds__(256) wconv_kernel(WPtrs p, bf16* Wth, bf16* Wtl) {
    int m = blockIdx.z;
    int colsM = p.cols[m];
    int c0 = blockIdx.x * 32, k0 = blockIdx.y * 32;
    if (c0 >= colsM) return;
    __shared__ float t[32][33];
    int tx = threadIdx.x & 31, ty = threadIdx.x >> 5;
    const float* W = p.w[m];
#pragma unroll
    for (int i = 0; i < 4; i++) {
        int k = k0 + ty + 8 * i;
        t[ty + 8 * i][tx] = W[(size_t)k * colsM + c0 + tx];
    }
    __syncthreads();
    size_t slot = (size_t)m * 256 * 128;
#pragma unroll
    for (int i = 0; i < 4; i++) {
        int col = c0 + ty + 8 * i;
        int kk = k0 + tx;
        float v = t[tx][ty + 8 * i];
        bf16 h, l; split_bf16(v, h, l);
        Wth[slot + (size_t)col * 128 + kk] = h;
        Wtl[slot + (size_t)col * 128 + kk] = l;
    }
}

// ---------------- fc0 -> split bf16 ----------------
__global__ void __launch_bounds__(256) fc0_kernel(
    const float* __restrict__ x, const float* __restrict__ w,
    const float* __restrict__ b, bf16* __restrict__ Xh, bf16* __restrict__ Xl)
{
    int idx = blockIdx.x * 256 + threadIdx.x;
    int n = idx >> 7, c = idx & 127;
    float x0 = x[n * 3 + 0], x1 = x[n * 3 + 1], x2 = x[n * 3 + 2];
    float v = fmaf(x0, w[c], fmaf(x1, w[128 + c], fmaf(x2, w[256 + c], b[c])));
    bf16 h, l; split_bf16(v, h, l);
    Xh[idx] = h; Xl[idx] = l;
}

// ---------------- batched (uniform-terms) tensor-core GEMM, 128 rows per CTA ----------------
// mode: 0=f32, 1=f32+gelu, 2=bf16, 3=bf16 transposed, 4=e4m3 row-major
struct GSlot { const bf16* Wh; const bf16* Wl; const float* bias; void* out; int M; int mode; };
struct GBatch { GSlot s[4]; };

#define GEMM_SMEM_1 (64 * TROW + 128 * TROW)
#define GEMM_SMEM_3 (2 * (64 * TROW + 128 * TROW))

template<int TERMS>
__global__ void __launch_bounds__(256) batched_gemm_kernel(
    const bf16* __restrict__ Xh, const bf16* __restrict__ Xl, GBatch args)
{
    extern __shared__ char sm[];
    char* sXh = sm;
    char* sWh = sm + 64 * TROW;
    char* sXl = sWh + 128 * TROW;
    char* sWl = sXl + 64 * TROW;

    GSlot sl = args.s[blockIdx.y];
    int tid = threadIdx.x, wid = tid >> 5, lane = tid & 31;
    int row_base = blockIdx.x * 128;

    copy_x64_async(sXh, Xh + (size_t)row_base * 128, tid);
    copy_tile_async(sWh, sl.Wh, 128, tid);
    if (TERMS == 3) {
        copy_x64_async(sXl, Xl + (size_t)row_base * 128, tid);
        copy_tile_async(sWl, sl.Wl, 128, tid);
    }
    CP_COMMIT();
    CP_WAIT0();
    __syncthreads();

    int rowBlk = wid & 3, colHalf = wid >> 2;
    uint32_t tb_off = (lane & 7) * TROW + (lane >> 3) * 16;
    uint32_t whB = smem_u32(sWh), wlB = smem_u32(sWl);
    uint32_t xfrag = (uint32_t)(rowBlk * 16 + (lane & 15)) * TROW + (uint32_t)(lane >> 4) * 16;
    int g = lane >> 2, tig = lane & 3;
    int M = sl.M, mode = sl.mode;

#pragma unroll
    for (int h2 = 0; h2 < 2; h2++) {
        uint32_t ah[8][4], al[8][4];
        {
            uint32_t qb_ = smem_u32(sXh) + xfrag;
#pragma unroll
            for (int kb = 0; kb < 8; kb++) ldsm4(ah[kb], qb_ + kb * 32);
            if (TERMS == 3) {
                uint32_t ql_ = smem_u32(sXl) + xfrag;
#pragma unroll
                for (int kb = 0; kb < 8; kb++) ldsm4(al[kb], ql_ + kb * 32);
            }
        }
        __syncthreads();
        if (h2 == 0) {
            copy_x64_async(sXh, Xh + (size_t)(row_base + 64) * 128, tid);
            if (TERMS == 3) copy_x64_async(sXl, Xl + (size_t)(row_base + 64) * 128, tid);
            CP_COMMIT();
        }

        float acc[8][4];
#pragma unroll
        for (int nb = 0; nb < 8; nb++)
#pragma unroll
            for (int j = 0; j < 4; j++) acc[nb][j] = 0.f;

#pragma unroll
        for (int nb = 0; nb < 8; nb++) {
            uint32_t kf[16];
            uint32_t a = whB + (colHalf * 8 + nb) * (8 * TROW) + tb_off;
#pragma unroll
            for (int q = 0; q < 4; q++) ldsm4(kf + 4 * q, a + q * 64);
#pragma unroll
            for (int s = 0; s < 8; s++) mma16816(acc[nb], ah[s], kf[2 * s], kf[2 * s + 1]);
            if (TERMS == 3) {
#pragma unroll
                for (int s = 0; s < 8; s++) mma16816(acc[nb], al[s], kf[2 * s], kf[2 * s + 1]);
                uint32_t kl[16];
                uint32_t a2 = wlB + (colHalf * 8 + nb) * (8 * TROW) + tb_off;
#pragma unroll
                for (int q = 0; q < 4; q++) ldsm4(kl + 4 * q, a2 + q * 64);
#pragma unroll
                for (int s = 0; s < 8; s++) mma16816(acc[nb], ah[s], kl[2 * s], kl[2 * s + 1]);
            }
        }

        int r0 = row_base + h2 * 64 + rowBlk * 16 + g, r1 = r0 + 8;
#pragma unroll
        for (int nb = 0; nb < 8; nb++) {
            int col = colHalf * 64 + nb * 8 + tig * 2;
            float b0 = sl.bias[col], b1 = sl.bias[col + 1];
            float v00 = acc[nb][0] + b0, v01 = acc[nb][1] + b1;
            float v10 = acc[nb][2] + b0, v11 = acc[nb][3] + b1;
            if (mode == 1) { v00 = gelu_f(v00); v01 = gelu_f(v01); v10 = gelu_f(v10); v11 = gelu_f(v11); }
            if (mode <= 1) {
                float* C = (float*)sl.out;
                *(float2*)&C[(size_t)r0 * M + col] = make_float2(v00, v01);
                *(float2*)&C[(size_t)r1 * M + col] = make_float2(v10, v11);
            } else if (mode == 2) {
                bf16* Cb = (bf16*)sl.out;
                *(uint32_t*)&Cb[(size_t)r0 * M + col] = pack_bf16(v00, v01);
                *(uint32_t*)&Cb[(size_t)r1 * M + col] = pack_bf16(v10, v11);
            } else if (mode == 3) {
                bf16* Cb = (bf16*)sl.out;
                Cb[(size_t)col * NTOK + r0]       = __float2bfloat16(v00);
                Cb[(size_t)(col + 1) * NTOK + r0] = __float2bfloat16(v01);
                Cb[(size_t)col * NTOK + r1]       = __float2bfloat16(v10);
                Cb[(size_t)(col + 1) * NTOK + r1] = __float2bfloat16(v11);
            } else {   // e4m3 row-major
                uint8_t* C8 = (uint8_t*)sl.out;
                *(uint16_t*)&C8[(size_t)r0 * M + col] = pack_e4m3(v00, v01);
                *(uint16_t*)&C8[(size_t)r1 * M + col] = pack_e4m3(v10, v11);
            }
        }

        if (h2 == 0) {
            CP_WAIT0();
            __syncthreads();
        }
    }
}

// ---------------- flash attention: fp8 scores, bf16 PV ----------------
// Q,K: e4m3 [N,128]; Vt: bf16 [128][NTOK]. smem: Q8 + 2*K8 + 2*Vbf16.
#define FK_SMEM (3 * TILE8_BYTES + 2 * TILE_BYTES)   // 124928
#define SC2F (0.088388347761972741f * 1.4426950408889634f)   // 1/sqrt(128)*log2(e)

__global__ void __launch_bounds__(256) flash_mma_kernel(
    const uint8_t* __restrict__ Q, const uint8_t* __restrict__ K,
    const bf16* __restrict__ Vt, float* __restrict__ Opart, float* __restrict__ Lpart)
{
    extern __shared__ char sm[];
    char* sQ = sm;
    char* sK[2] = { sm + TILE8_BYTES, sm + 2 * TILE8_BYTES };
    char* sV[2] = { sm + 3 * TILE8_BYTES, sm + 3 * TILE8_BYTES + TILE_BYTES };

    int tid = threadIdx.x, wid = tid >> 5, lane = tid & 31;
    int qb = blockIdx.x >> 1, part = blockIdx.x & 1;
    int key0 = part * 4096;

    copy_tile8_async(sQ,    Q  + (size_t)(qb * 128) * 128, tid);
    copy_tile8_async(sK[0], K  + (size_t)key0 * 128, tid);
    copy_tile_async (sV[0], Vt + key0, NTOK, tid);
    CP_COMMIT();
    copy_tile8_async(sK[1], K  + (size_t)(key0 + 128) * 128, tid);
    copy_tile_async (sV[1], Vt + key0 + 128, NTOK, tid);
    CP_COMMIT();

    CP_WAIT1();
    __syncthreads();

    // Q fragments: 4 k32-blocks x 4 regs (fp8)
    uint32_t qf[4][4];
    {
        uint32_t qbase = smem_u32(sQ) + (wid * 16 + (lane & 15)) * KROW + (lane >> 4) * 16;
#pragma unroll
        for (int kb = 0; kb < 4; kb++) ldsm4(qf[kb], qbase + kb * 32);
    }

    float oacc[16][4];
#pragma unroll
    for (int nb = 0; nb < 16; nb++)
#pragma unroll
        for (int j = 0; j < 4; j++) oacc[nb][j] = 0.f;
    float lacc0 = 0.f, lacc1 = 0.f;

    uint32_t tb8  = (lane & 7) * KROW + (lane >> 3) * 16;   // fp8 K tiles
    uint32_t tb16 = (lane & 7) * TROW + (lane >> 3) * 16;   // bf16 V tiles

    for (int i = 0; i < 32; i++) {
        int b = i & 1;
        CP_WAIT1();
        __syncthreads();

        uint32_t kB = smem_u32(sK[b]);
        uint32_t vB = smem_u32(sV[b]);
        uint32_t pf[8][4];

        // ---- S = Q K^T (fp8, k32 per mma), exp, pack P to bf16 ----
#pragma unroll
        for (int j = 0; j < 8; j++) {
            float s0[4] = {0.f, 0.f, 0.f, 0.f};
            float s1[4] = {0.f, 0.f, 0.f, 0.f};
            uint32_t kf[8];
            uint32_t a0 = kB + (uint32_t)(2 * j) * (8 * KROW) + tb8;
            ldsm4(kf, a0);
            ldsm4(kf + 4, a0 + 64);
#pragma unroll
            for (int s = 0; s < 4; s++) mma16832f8(s0, qf[s], kf[2 * s], kf[2 * s + 1]);
            uint32_t a1 = kB + (uint32_t)(2 * j + 1) * (8 * KROW) + tb8;
            ldsm4(kf, a1);
            ldsm4(kf + 4, a1 + 64);
#pragma unroll
            for (int s = 0; s < 4; s++) mma16832f8(s1, qf[s], kf[2 * s], kf[2 * s + 1]);

            float e00 = ex2(s0[0] * SC2F), e01 = ex2(s0[1] * SC2F);
            float e02 = ex2(s0[2] * SC2F), e03 = ex2(s0[3] * SC2F);
            float e10 = ex2(s1[0] * SC2F), e11 = ex2(s1[1] * SC2F);
            float e12 = ex2(s1[2] * SC2F), e13 = ex2(s1[3] * SC2F);
            lacc0 += (e00 + e01) + (e10 + e11);
            lacc1 += (e02 + e03) + (e12 + e13);
            pf[j][0] = pack_bf16(e00, e01);
            pf[j][1] = pack_bf16(e02, e03);
            pf[j][2] = pack_bf16(e10, e11);
            pf[j][3] = pack_bf16(e12, e13);
        }

        // ---- O += P V (bf16) ----
#pragma unroll
        for (int nb = 0; nb < 16; nb++) {
            uint32_t vf[16];
            uint32_t a = vB + nb * (8 * TROW) + tb16;
#pragma unroll
            for (int q = 0; q < 4; q++) ldsm4(vf + 4 * q, a + q * 64);
#pragma unroll
            for (int s = 0; s < 8; s++) mma16816(oacc[nb], pf[s], vf[2 * s], vf[2 * s + 1]);
        }

        __syncthreads();
        if (i + 2 < 32) {
            copy_tile8_async(sK[b], K  + (size_t)(key0 + (i + 2) * 128) * 128, tid);
            copy_tile_async (sV[b], Vt + key0 + (i + 2) * 128, NTOK, tid);
        }
        CP_COMMIT();
    }

    int g = lane >> 2, tig = lane & 3;
    int row0 = qb * 128 + wid * 16 + g;
    float* o0 = Opart + ((size_t)part * NTOK + row0) * 128;
    float* o1 = o0 + 8 * 128;
#pragma unroll
    for (int nb = 0; nb < 16; nb++) {
        *(float2*)&o0[nb * 8 + tig * 2] = make_float2(oacc[nb][0], oacc[nb][1]);
        *(float2*)&o1[nb * 8 + tig * 2] = make_float2(oacc[nb][2], oacc[nb][3]);
    }
    lacc0 += __shfl_xor_sync(0xffffffffu, lacc0, 1);
    lacc0 += __shfl_xor_sync(0xffffffffu, lacc0, 2);
    lacc1 += __shfl_xor_sync(0xffffffffu, lacc1, 1);
    lacc1 += __shfl_xor_sync(0xffffffffu, lacc1, 2);
    if (tig == 0) {
        Lpart[part * NTOK + row0]     = lacc0;
        Lpart[part * NTOK + row0 + 8] = lacc1;
    }
}

// ---------------- combine split-2 partials + residual (+gelu) -> split bf16 ----------------
__global__ void __launch_bounds__(256) combine_kernel(
    const float* __restrict__ Op, const float* __restrict__ Lp,
    const float* __restrict__ R, bf16* __restrict__ Xh, bf16* __restrict__ Xl, int applyGelu)
{
    int idx = blockIdx.x * 256 + threadIdx.x;
    int row = idx >> 7;
    float l = Lp[row] + Lp[NTOK + row];
    float o = (Op[idx] + Op[(size_t)NTOK * 128 + idx]) * (1.0f / (l * 8192.0f));
    float v = o + R[idx];
    if (applyGelu) v = gelu_f(v);
    bf16 h, lo; split_bf16(v, h, lo);
    Xh[idx] = h; Xl[idx] = lo;
}

// ---------------- local attention -> split bf16 ----------------
__global__ void __launch_bounds__(256) local_attn_kernel(
    const float* __restrict__ Q, const float* __restrict__ K,
    const float* __restrict__ V, const int* __restrict__ nbr,
    const float* __restrict__ R, bf16* __restrict__ Xh, bf16* __restrict__ Xl)
{
    __shared__ float qs[8][128];
    __shared__ float ps[8][8][32];
    __shared__ int   js[8][32];
    int w = threadIdx.x >> 5, lane = threadIdx.x & 31;
    int n = blockIdx.x * 8 + w;

    float4 qv = *(const float4*)&Q[n * 128 + lane * 4];
    *(float4*)&qs[w][lane * 4] = make_float4(qv.x * 0.25f, qv.y * 0.25f, qv.z * 0.25f, qv.w * 0.25f);
    int j = nbr[n * 32 + lane];
    js[w][lane] = j;
    __syncwarp();

    const float* krow = K + (size_t)j * 128;
    float sc[8];
#pragma unroll
    for (int h = 0; h < 8; h++) {
        float4 a0 = *(const float4*)&krow[h * 16 + 0];
        float4 a1 = *(const float4*)&krow[h * 16 + 4];
        float4 a2 = *(const float4*)&krow[h * 16 + 8];
        float4 a3 = *(const float4*)&krow[h * 16 + 12];
        const float* q = &qs[w][h * 16];
        sc[h] = q[0]*a0.x + q[1]*a0.y + q[2]*a0.z + q[3]*a0.w
              + q[4]*a1.x + q[5]*a1.y + q[6]*a1.z + q[7]*a1.w
              + q[8]*a2.x + q[9]*a2.y + q[10]*a2.z + q[11]*a2.w
              + q[12]*a3.x + q[13]*a3.y + q[14]*a3.z + q[15]*a3.w;
    }
#pragma unroll
    for (int h = 0; h < 8; h++) {
        float mx = sc[h];
#pragma unroll
        for (int o = 16; o; o >>= 1) mx = fmaxf(mx, __shfl_xor_sync(0xffffffffu, mx, o));
        float p = __expf(sc[h] - mx);
        float su = p;
#pragma unroll
        for (int o = 16; o; o >>= 1) su += __shfl_xor_sync(0xffffffffu, su, o);
        ps[w][h][lane] = p / su;
    }
    __syncwarp();

    float acc[4] = {0.f, 0.f, 0.f, 0.f};
#pragma unroll 4
    for (int k = 0; k < 32; k++) {
        int jj = js[w][k];
        const float* vrow = V + (size_t)jj * 128;
#pragma unroll
        for (int i = 0; i < 4; i++) {
            int c = lane + 32 * i;
            acc[i] += ps[w][c >> 4][k] * vrow[c];
        }
    }
#pragma unroll
    for (int i = 0; i < 4; i++) {
        int c = lane + 32 * i;
        float v = gelu_f(acc[i] + R[n * 128 + c]);
        bf16 h, lo; split_bf16(v, h, lo);
        Xh[n * 128 + c] = h; Xl[n * 128 + c] = lo;
    }
}

// ---------------- fc2 ----------------
__global__ void __launch_bounds__(256) fc2_kernel(
    const float* __restrict__ H, const float* __restrict__ w,
    const float* __restrict__ b, float* __restrict__ out)
{
    int n = (blockIdx.x * 256 + threadIdx.x) >> 5;
    int lane = threadIdx.x & 31;
    const float4* h4 = (const float4*)(H + (size_t)n * 256);
    const float4* w4 = (const float4*)w;
    float acc = 0.f;
#pragma unroll
    for (int i = 0; i < 2; i++) {
        float4 hv = h4[lane + 32 * i];
        float4 wv = w4[lane + 32 * i];
        acc += hv.x * wv.x + hv.y * wv.y + hv.z * wv.z + hv.w * wv.w;
    }
#pragma unroll
    for (int o = 16; o; o >>= 1) acc += __shfl_xor_sync(0xffffffffu, acc, o);
    if (!lane) out[n] = acc + b[0];
}

// ---------------- host orchestration ----------------
extern "C" void kernel_launch(void* const* d_in, const int* in_sizes, int n_in,
                              void* d_out, int out_size)
{
    (void)in_sizes; (void)n_in; (void)out_size;
    const float* x    = (const float*)d_in[0];
    const float* fc0w = (const float*)d_in[1];
    const float* fc0b = (const float*)d_in[2];
    const float* fc1b = (const float*)d_in[28];
    const float* fc2w = (const float*)d_in[29];
    const float* fc2b = (const float*)d_in[30];
    const int*   nbr  = (const int*)d_in[31];

    float *Qb, *Kb, *Vb, *Rb, *H, *L;
    bf16 *Xh, *Xl, *Wth, *Wtl;
    cudaGetSymbolAddress((void**)&Qb, g_Qb);
    cudaGetSymbolAddress((void**)&Kb, g_Kb);
    cudaGetSymbolAddress((void**)&Vb, g_Vb);
    cudaGetSymbolAddress((void**)&Rb, g_Rb);
    cudaGetSymbolAddress((void**)&H,  g_H);
    cudaGetSymbolAddress((void**)&L,  g_L);
    cudaGetSymbolAddress((void**)&Xh, g_Xh);
    cudaGetSymbolAddress((void**)&Xl, g_Xl);
    cudaGetSymbolAddress((void**)&Wth, g_Wth);
    cudaGetSymbolAddress((void**)&Wtl, g_Wtl);

    cudaFuncSetAttribute(flash_mma_kernel, cudaFuncAttributeMaxDynamicSharedMemorySize, FK_SMEM);
    cudaFuncSetAttribute(batched_gemm_kernel<1>, cudaFuncAttributeMaxDynamicSharedMemorySize, GEMM_SMEM_1);
    cudaFuncSetAttribute(batched_gemm_kernel<3>, cudaFuncAttributeMaxDynamicSharedMemorySize, GEMM_SMEM_3);

    static cudaStream_t sSide = nullptr;
    static cudaEvent_t evForkW, evWconv, evFork0, evW0, evFork2, evW2;
    if (!sSide) {
        cudaStreamCreateWithFlags(&sSide, cudaStreamNonBlocking);
        cudaEventCreateWithFlags(&evForkW, cudaEventDisableTiming);
        cudaEventCreateWithFlags(&evWconv, cudaEventDisableTiming);
        cudaEventCreateWithFlags(&evFork0, cudaEventDisableTiming);
        cudaEventCreateWithFlags(&evW0,    cudaEventDisableTiming);
        cudaEventCreateWithFlags(&evFork2, cudaEventDisableTiming);
        cudaEventCreateWithFlags(&evW2,    cudaEventDisableTiming);
    }

    // fork first, then wconv on side concurrent with fc0 on main
    cudaEventRecord(evForkW, 0);
    cudaStreamWaitEvent(sSide, evForkW, 0);
    {
        WPtrs p;
        for (int i = 0; i < 3; i++) {
            p.w[4 * i + 0] = (const float*)d_in[3 + 8 * i];
            p.w[4 * i + 1] = (const float*)d_in[5 + 8 * i];
            p.w[4 * i + 2] = (const float*)d_in[7 + 8 * i];
            p.w[4 * i + 3] = (const float*)d_in[9 + 8 * i];
            p.cols[4 * i + 0] = p.cols[4 * i + 1] = p.cols[4 * i + 2] = p.cols[4 * i + 3] = 128;
        }
        p.w[12] = (const float*)d_in[27];
        p.cols[12] = 256;
        wconv_kernel<<<dim3(8, 4, 13), 256, 0, sSide>>>(p, Wth, Wtl);
        cudaEventRecord(evWconv, sSide);
    }
    const size_t SLOT = 256 * 128;

    fc0_kernel<<<NTOK * 128 / 256, 256>>>(x, fc0w, fc0b, Xh, Xl);
    cudaStreamWaitEvent(0, evWconv, 0);

    dim3 gQKV(NTOK / 128, 3), gL1(NTOK / 128, 4), gW(NTOK / 128, 1), gFC1(NTOK / 128, 2);

    // ---- layer 0 (global, gelu): Q,K fp8; V bf16T; W f32 3-term on side ----
    {
        cudaEventRecord(evFork0, 0);
        cudaStreamWaitEvent(sSide, evFork0, 0);
        GBatch w;
        w.s[0] = { Wth + 3*SLOT, Wtl + 3*SLOT, (const float*)d_in[10], Rb, 128, 0 };
        batched_gemm_kernel<3><<<gW, 256, GEMM_SMEM_3, sSide>>>(Xh, Xl, w);
        cudaEventRecord(evW0, sSide);

        GBatch qkv;
        qkv.s[0] = { Wth + 0*SLOT, Wtl + 0*SLOT, (const float*)d_in[4], Qb, 128, 4 };
        qkv.s[1] = { Wth + 1*SLOT, Wtl + 1*SLOT, (const float*)d_in[6], Kb, 128, 4 };
        qkv.s[2] = { Wth + 2*SLOT, Wtl + 2*SLOT, (const float*)d_in[8], Vb, 128, 3 };
        batched_gemm_kernel<1><<<gQKV, 256, GEMM_SMEM_1>>>(Xh, Xl, qkv);
        flash_mma_kernel<<<128, 256, FK_SMEM>>>((const uint8_t*)Qb, (const uint8_t*)Kb, (const bf16*)Vb, H, L);
        cudaStreamWaitEvent(0, evW0, 0);
        combine_kernel<<<NTOK * 128 / 256, 256>>>(H, L, Rb, Xh, Xl, 1);
    }

    // ---- layer 1 (local, gelu): all 3-term, one batched launch ----
    {
        GBatch a;
        a.s[0] = { Wth + 4*SLOT, Wtl + 4*SLOT, (const float*)d_in[12], Qb, 128, 0 };
        a.s[1] = { Wth + 5*SLOT, Wtl + 5*SLOT, (const float*)d_in[14], Kb, 128, 0 };
        a.s[2] = { Wth + 6*SLOT, Wtl + 6*SLOT, (const float*)d_in[16], Vb, 128, 0 };
        a.s[3] = { Wth + 7*SLOT, Wtl + 7*SLOT, (const float*)d_in[18], Rb, 128, 0 };
        batched_gemm_kernel<3><<<gL1, 256, GEMM_SMEM_3>>>(Xh, Xl, a);
        local_attn_kernel<<<NTOK / 8, 256>>>(Qb, Kb, Vb, nbr, Rb, Xh, Xl);
    }

    // ---- layer 2 (global, no act): same pattern ----
    {
        cudaEventRecord(evFork2, 0);
        cudaStreamWaitEvent(sSide, evFork2, 0);
        GBatch w;
        w.s[0] = { Wth + 11*SLOT, Wtl + 11*SLOT, (const float*)d_in[26], Rb, 128, 0 };
        batched_gemm_kernel<3><<<gW, 256, GEMM_SMEM_3, sSide>>>(Xh, Xl, w);
        cudaEventRecord(evW2, sSide);

        GBatch qkv;
        qkv.s[0] = { Wth + 8*SLOT,  Wtl + 8*SLOT,  (const float*)d_in[20], Qb, 128, 4 };
        qkv.s[1] = { Wth + 9*SLOT,  Wtl + 9*SLOT,  (const float*)d_in[22], Kb, 128, 4 };
        qkv.s[2] = { Wth + 10*SLOT, Wtl + 10*SLOT, (const float*)d_in[24], Vb, 128, 3 };
        batched_gemm_kernel<1><<<gQKV, 256, GEMM_SMEM_1>>>(Xh, Xl, qkv);
        flash_mma_kernel<<<128, 256, FK_SMEM>>>((const uint8_t*)Qb, (const uint8_t*)Kb, (const bf16*)Vb, H, L);
        cudaStreamWaitEvent(0, evW2, 0);
        combine_kernel<<<NTOK * 128 / 256, 256>>>(H, L, Rb, Xh, Xl, 0);
    }

    // fc1 (3-term, gelu) + fc2
    {
        GBatch a;
        a.s[0] = { Wth + 12*SLOT,             Wtl + 12*SLOT,             fc1b,       H,       256, 1 };
        a.s[1] = { Wth + 12*SLOT + 128 * 128, Wtl + 12*SLOT + 128 * 128, fc1b + 128, H + 128, 256, 1 };
        batched_gemm_kernel<3><<<gFC1, 256, GEMM_SMEM_3>>>(Xh, Xl, a);
    }
    fc2_kernel<<<NTOK * 32 / 256, 256>>>(H, fc2w, fc2b, (float*)d_out);
}

// round 16
// speedup vs baseline: 1.1288x; 1.1288x over previous
#include <cuda_runtime.h>
#include <cuda_bf16.h>
#include <math.h>
#include <cstdint>

#define NTOK 8192
typedef unsigned long long u64;
typedef __nv_bfloat16 bf16;

// ---------------- scratch ----------------
__device__ float g_Qb[NTOK * 128];
__device__ float g_Kb[NTOK * 128];
__device__ float g_Vb[NTOK * 128];
__device__ float g_Rb[NTOK * 128];
__device__ float g_H[NTOK * 256];      // reused as O partials (2 x 1M floats)
__device__ float g_L[2 * NTOK];
__device__ bf16  g_Xh[NTOK * 128];
__device__ bf16  g_Xl[NTOK * 128];
__device__ bf16  g_Wth[13 * 256 * 128];
__device__ bf16  g_Wtl[13 * 256 * 128];

// ---------------- helpers ----------------
__device__ __forceinline__ float gelu_f(float x) {
    return 0.5f * x * (1.0f + erff(x * 0.7071067811865476f));
}
__device__ __forceinline__ uint32_t pack_bf16(float lo, float hi) {
    uint32_t r; asm("cvt.rn.bf16x2.f32 %0, %1, %2;" : "=r"(r) : "f"(hi), "f"(lo)); return r;
}
__device__ __forceinline__ uint32_t smem_u32(const void* p) {
    uint32_t a; asm("{ .reg .u64 t; cvta.to.shared.u64 t, %1; cvt.u32.u64 %0, t; }" : "=r"(a) : "l"(p));
    return a;
}
__device__ __forceinline__ void split_bf16(float v, bf16& h, bf16& l) {
    h = __float2bfloat16(v);
    l = __float2bfloat16(v - __bfloat162float(h));
}
__device__ __forceinline__ float ex2(float x) {
    float r; asm("ex2.approx.ftz.f32 %0, %1;" : "=f"(r) : "f"(x)); return r;
}

// ---------------- mma.sync / ldmatrix / cp.async primitives ----------------
__device__ __forceinline__ void mma16816(float* c, const uint32_t* a, uint32_t b0, uint32_t b1) {
    asm volatile("mma.sync.aligned.m16n8k16.row.col.f32.bf16.bf16.f32 "
        "{%0,%1,%2,%3}, {%4,%5,%6,%7}, {%8,%9}, {%0,%1,%2,%3};"
        : "+f"(c[0]), "+f"(c[1]), "+f"(c[2]), "+f"(c[3])
        : "r"(a[0]), "r"(a[1]), "r"(a[2]), "r"(a[3]), "r"(b0), "r"(b1));
}
__device__ __forceinline__ void ldsm4(uint32_t* r, uint32_t addr) {
    asm volatile("ldmatrix.sync.aligned.m8n8.x4.shared.b16 {%0,%1,%2,%3}, [%4];"
        : "=r"(r[0]), "=r"(r[1]), "=r"(r[2]), "=r"(r[3]) : "r"(addr));
}
__device__ __forceinline__ void cp16(uint32_t sdst, const void* gsrc) {
    asm volatile("cp.async.cg.shared.global [%0], [%1], 16;" :: "r"(sdst), "l"(gsrc));
}
#define CP_COMMIT() asm volatile("cp.async.commit_group;" ::: "memory")
#define CP_WAIT1()  asm volatile("cp.async.wait_group 1;" ::: "memory")
#define CP_WAIT0()  asm volatile("cp.async.wait_group 0;" ::: "memory")

// tile geometry: 128 rows x 128 bf16, rows padded to 272 bytes
#define TROW 272
#define TILE_BYTES (128 * TROW)

__device__ __forceinline__ void copy_tile_async(char* dst, const bf16* __restrict__ src,
                                                int rstride, int tid) {
    uint32_t d = smem_u32(dst);
#pragma unroll
    for (int rep = 0; rep < 8; rep++) {
        int chunk = rep * 256 + tid;       // 2048 chunks of 16B
        int r = chunk >> 4, c = chunk & 15;
        cp16(d + r * TROW + c * 16, src + (size_t)r * rstride + c * 8);
    }
}
__device__ __forceinline__ void copy_x64_async(char* dst, const bf16* __restrict__ src, int tid) {
    uint32_t d = smem_u32(dst);
#pragma unroll
    for (int rep = 0; rep < 4; rep++) {
        int chunk = rep * 256 + tid;       // 1024 chunks (64 rows)
        int r = chunk >> 4, c = chunk & 15;
        cp16(d + r * TROW + c * 16, src + (size_t)r * 128 + c * 8);
    }
}

// ---------------- weight transpose + bf16 split (once per launch) ----------------
struct WPtrs { const float* w[13]; int cols[13]; };

__global__ void __launch_bounds__(256) wconv_kernel(WPtrs p, bf16* Wth, bf16* Wtl) {
    int m = blockIdx.z;
    int colsM = p.cols[m];
    int c0 = blockIdx.x * 32, k0 = blockIdx.y * 32;
    if (c0 >= colsM) return;
    __shared__ float t[32][33];
    int tx = threadIdx.x & 31, ty = threadIdx.x >> 5;
    const float* W = p.w[m];
#pragma unroll
    for (int i = 0; i < 4; i++) {
        int k = k0 + ty + 8 * i;
        t[ty + 8 * i][tx] = W[(size_t)k * colsM + c0 + tx];
    }
    __syncthreads();
    size_t slot = (size_t)m * 256 * 128;
#pragma unroll
    for (int i = 0; i < 4; i++) {
        int col = c0 + ty + 8 * i;
        int kk = k0 + tx;
        float v = t[tx][ty + 8 * i];
        bf16 h, l; split_bf16(v, h, l);
        Wth[slot + (size_t)col * 128 + kk] = h;
        Wtl[slot + (size_t)col * 128 + kk] = l;
    }
}

// ---------------- fc0 -> split bf16 ----------------
__global__ void __launch_bounds__(256) fc0_kernel(
    const float* __restrict__ x, const float* __restrict__ w,
    const float* __restrict__ b, bf16* __restrict__ Xh, bf16* __restrict__ Xl)
{
    int idx = blockIdx.x * 256 + threadIdx.x;
    int n = idx >> 7, c = idx & 127;
    float x0 = x[n * 3 + 0], x1 = x[n * 3 + 1], x2 = x[n * 3 + 2];
    float v = fmaf(x0, w[c], fmaf(x1, w[128 + c], fmaf(x2, w[256 + c], b[c])));
    bf16 h, l; split_bf16(v, h, l);
    Xh[idx] = h; Xl[idx] = l;
}

// ---------------- batched tensor-core GEMM ----------------
// R128=1: 128 rows per CTA (two 64-row halves, half-1 X copy hidden under half-0).
// R128=0: 64 rows per CTA (R11-measured best for 1-term QKV).
struct GSlot { const bf16* Wh; const bf16* Wl; const float* bias; void* out; int M; int mode; };
struct GBatch { GSlot s[4]; };

#define GEMM_SMEM_1 (64 * TROW + 128 * TROW)
#define GEMM_SMEM_3 (2 * (64 * TROW + 128 * TROW))

template<int TERMS, int R128>
__global__ void __launch_bounds__(256) batched_gemm_kernel(
    const bf16* __restrict__ Xh, const bf16* __restrict__ Xl, GBatch args)
{
    extern __shared__ char sm[];
    char* sXh = sm;
    char* sWh = sm + 64 * TROW;
    char* sXl = sWh + 128 * TROW;
    char* sWl = sXl + 64 * TROW;

    GSlot sl = args.s[blockIdx.y];
    int tid = threadIdx.x, wid = tid >> 5, lane = tid & 31;
    int row_base = blockIdx.x * (R128 ? 128 : 64);

    copy_x64_async(sXh, Xh + (size_t)row_base * 128, tid);
    copy_tile_async(sWh, sl.Wh, 128, tid);
    if (TERMS == 3) {
        copy_x64_async(sXl, Xl + (size_t)row_base * 128, tid);
        copy_tile_async(sWl, sl.Wl, 128, tid);
    }
    CP_COMMIT();
    CP_WAIT0();
    __syncthreads();

    int rowBlk = wid & 3, colHalf = wid >> 2;
    uint32_t tb_off = (lane & 7) * TROW + (lane >> 3) * 16;
    uint32_t whB = smem_u32(sWh), wlB = smem_u32(sWl);
    uint32_t xfrag = (uint32_t)(rowBlk * 16 + (lane & 15)) * TROW + (uint32_t)(lane >> 4) * 16;
    int g = lane >> 2, tig = lane & 3;
    int M = sl.M, mode = sl.mode;

#pragma unroll
    for (int h2 = 0; h2 < (R128 ? 2 : 1); h2++) {
        uint32_t ah[8][4], al[8][4];
        {
            uint32_t qb_ = smem_u32(sXh) + xfrag;
#pragma unroll
            for (int kb = 0; kb < 8; kb++) ldsm4(ah[kb], qb_ + kb * 32);
            if (TERMS == 3) {
                uint32_t ql_ = smem_u32(sXl) + xfrag;
#pragma unroll
                for (int kb = 0; kb < 8; kb++) ldsm4(al[kb], ql_ + kb * 32);
            }
        }
        if (R128) {
            __syncthreads();   // all warps hold X fragments; X smem free to overwrite
            if (h2 == 0) {
                copy_x64_async(sXh, Xh + (size_t)(row_base + 64) * 128, tid);
                if (TERMS == 3) copy_x64_async(sXl, Xl + (size_t)(row_base + 64) * 128, tid);
                CP_COMMIT();
            }
        }

        float acc[8][4];
#pragma unroll
        for (int nb = 0; nb < 8; nb++)
#pragma unroll
            for (int j = 0; j < 4; j++) acc[nb][j] = 0.f;

#pragma unroll
        for (int nb = 0; nb < 8; nb++) {
            uint32_t kf[16];
            uint32_t a = whB + (colHalf * 8 + nb) * (8 * TROW) + tb_off;
#pragma unroll
            for (int q = 0; q < 4; q++) ldsm4(kf + 4 * q, a + q * 64);
#pragma unroll
            for (int s = 0; s < 8; s++) mma16816(acc[nb], ah[s], kf[2 * s], kf[2 * s + 1]);
            if (TERMS == 3) {
#pragma unroll
                for (int s = 0; s < 8; s++) mma16816(acc[nb], al[s], kf[2 * s], kf[2 * s + 1]);
                uint32_t kl[16];
                uint32_t a2 = wlB + (colHalf * 8 + nb) * (8 * TROW) + tb_off;
#pragma unroll
                for (int q = 0; q < 4; q++) ldsm4(kl + 4 * q, a2 + q * 64);
#pragma unroll
                for (int s = 0; s < 8; s++) mma16816(acc[nb], ah[s], kl[2 * s], kl[2 * s + 1]);
            }
        }

        int r0 = row_base + h2 * 64 + rowBlk * 16 + g, r1 = r0 + 8;
#pragma unroll
        for (int nb = 0; nb < 8; nb++) {
            int col = colHalf * 64 + nb * 8 + tig * 2;
            float b0 = sl.bias[col], b1 = sl.bias[col + 1];
            float v00 = acc[nb][0] + b0, v01 = acc[nb][1] + b1;
            float v10 = acc[nb][2] + b0, v11 = acc[nb][3] + b1;
            if (mode == 1) { v00 = gelu_f(v00); v01 = gelu_f(v01); v10 = gelu_f(v10); v11 = gelu_f(v11); }
            if (mode <= 1) {
                float* C = (float*)sl.out;
                *(float2*)&C[(size_t)r0 * M + col] = make_float2(v00, v01);
                *(float2*)&C[(size_t)r1 * M + col] = make_float2(v10, v11);
            } else if (mode == 2) {
                bf16* Cb = (bf16*)sl.out;
                *(uint32_t*)&Cb[(size_t)r0 * M + col] = pack_bf16(v00, v01);
                *(uint32_t*)&Cb[(size_t)r1 * M + col] = pack_bf16(v10, v11);
            } else {
                bf16* Cb = (bf16*)sl.out;
                Cb[(size_t)col * NTOK + r0]       = __float2bfloat16(v00);
                Cb[(size_t)(col + 1) * NTOK + r0] = __float2bfloat16(v01);
                Cb[(size_t)col * NTOK + r1]       = __float2bfloat16(v10);
                Cb[(size_t)(col + 1) * NTOK + r1] = __float2bfloat16(v11);
            }
        }

        if (R128 && h2 == 0) {
            CP_WAIT0();
            __syncthreads();
        }
    }
}

// ---------------- flash attention (R5-proven: 256 thr, 5 tiles, split-2) ----------------
#define FK_SMEM (5 * TILE_BYTES)
#define SC2F (0.088388347761972741f * 1.4426950408889634f)   // 1/sqrt(128)*log2(e)

__global__ void __launch_bounds__(256) flash_mma_kernel(
    const bf16* __restrict__ Q, const bf16* __restrict__ K,
    const bf16* __restrict__ Vt, float* __restrict__ Opart, float* __restrict__ Lpart)
{
    extern __shared__ char sm[];
    char* sQ = sm;
    char* sK[2] = { sm + TILE_BYTES, sm + 2 * TILE_BYTES };
    char* sV[2] = { sm + 3 * TILE_BYTES, sm + 4 * TILE_BYTES };

    int tid = threadIdx.x, wid = tid >> 5, lane = tid & 31;
    int qb = blockIdx.x >> 1, part = blockIdx.x & 1;
    int key0 = part * 4096;

    copy_tile_async(sQ,    Q  + (size_t)(qb * 128) * 128, 128, tid);
    copy_tile_async(sK[0], K  + (size_t)key0 * 128,       128, tid);
    copy_tile_async(sV[0], Vt + key0,                    NTOK, tid);
    CP_COMMIT();
    copy_tile_async(sK[1], K  + (size_t)(key0 + 128) * 128, 128, tid);
    copy_tile_async(sV[1], Vt + key0 + 128,                NTOK, tid);
    CP_COMMIT();

    CP_WAIT1();
    __syncthreads();

    uint32_t qf[8][4];
    {
        uint32_t qbase = smem_u32(sQ) + (wid * 16 + (lane & 15)) * TROW + (lane >> 4) * 16;
#pragma unroll
        for (int kb = 0; kb < 8; kb++) ldsm4(qf[kb], qbase + kb * 32);
    }

    float oacc[16][4];
#pragma unroll
    for (int nb = 0; nb < 16; nb++)
#pragma unroll
        for (int j = 0; j < 4; j++) oacc[nb][j] = 0.f;
    float lacc0 = 0.f, lacc1 = 0.f;

    uint32_t tb_off = (lane & 7) * TROW + (lane >> 3) * 16;

    for (int i = 0; i < 32; i++) {
        int b = i & 1;
        CP_WAIT1();
        __syncthreads();

        uint32_t kB = smem_u32(sK[b]);
        uint32_t vB = smem_u32(sV[b]);
        uint32_t pf[8][4];

#pragma unroll
        for (int j = 0; j < 8; j++) {
            float s0[4] = {0.f, 0.f, 0.f, 0.f};
            float s1[4] = {0.f, 0.f, 0.f, 0.f};
            uint32_t kf[16];
            uint32_t a0 = kB + (2 * j) * (8 * TROW) + tb_off;
#pragma unroll
            for (int q = 0; q < 4; q++) ldsm4(kf + 4 * q, a0 + q * 64);
#pragma unroll
            for (int s = 0; s < 8; s++) mma16816(s0, qf[s], kf[2 * s], kf[2 * s + 1]);
            uint32_t a1 = kB + (2 * j + 1) * (8 * TROW) + tb_off;
#pragma unroll
            for (int q = 0; q < 4; q++) ldsm4(kf + 4 * q, a1 + q * 64);
#pragma unroll
            for (int s = 0; s < 8; s++) mma16816(s1, qf[s], kf[2 * s], kf[2 * s + 1]);

            float e00 = ex2(s0[0] * SC2F), e01 = ex2(s0[1] * SC2F);
            float e02 = ex2(s0[2] * SC2F), e03 = ex2(s0[3] * SC2F);
            float e10 = ex2(s1[0] * SC2F), e11 = ex2(s1[1] * SC2F);
            float e12 = ex2(s1[2] * SC2F), e13 = ex2(s1[3] * SC2F);
            lacc0 += (e00 + e01) + (e10 + e11);
            lacc1 += (e02 + e03) + (e12 + e13);
            pf[j][0] = pack_bf16(e00, e01);
            pf[j][1] = pack_bf16(e02, e03);
            pf[j][2] = pack_bf16(e10, e11);
            pf[j][3] = pack_bf16(e12, e13);
        }

#pragma unroll
        for (int nb = 0; nb < 16; nb++) {
            uint32_t vf[16];
            uint32_t a = vB + nb * (8 * TROW) + tb_off;
#pragma unroll
            for (int q = 0; q < 4; q++) ldsm4(vf + 4 * q, a + q * 64);
#pragma unroll
            for (int s = 0; s < 8; s++) mma16816(oacc[nb], pf[s], vf[2 * s], vf[2 * s + 1]);
        }

        __syncthreads();
        if (i + 2 < 32) {
            copy_tile_async(sK[b], K  + (size_t)(key0 + (i + 2) * 128) * 128, 128, tid);
            copy_tile_async(sV[b], Vt + key0 + (i + 2) * 128,               NTOK, tid);
        }
        CP_COMMIT();
    }

    int g = lane >> 2, tig = lane & 3;
    int row0 = qb * 128 + wid * 16 + g;
    float* o0 = Opart + ((size_t)part * NTOK + row0) * 128;
    float* o1 = o0 + 8 * 128;
#pragma unroll
    for (int nb = 0; nb < 16; nb++) {
        *(float2*)&o0[nb * 8 + tig * 2] = make_float2(oacc[nb][0], oacc[nb][1]);
        *(float2*)&o1[nb * 8 + tig * 2] = make_float2(oacc[nb][2], oacc[nb][3]);
    }
    lacc0 += __shfl_xor_sync(0xffffffffu, lacc0, 1);
    lacc0 += __shfl_xor_sync(0xffffffffu, lacc0, 2);
    lacc1 += __shfl_xor_sync(0xffffffffu, lacc1, 1);
    lacc1 += __shfl_xor_sync(0xffffffffu, lacc1, 2);
    if (tig == 0) {
        Lpart[part * NTOK + row0]     = lacc0;
        Lpart[part * NTOK + row0 + 8] = lacc1;
    }
}

// ---------------- combine split-2 partials + residual (+gelu) -> split bf16 ----------------
__global__ void __launch_bounds__(256) combine_kernel(
    const float* __restrict__ Op, const float* __restrict__ Lp,
    const float* __restrict__ R, bf16* __restrict__ Xh, bf16* __restrict__ Xl, int applyGelu)
{
    int idx = blockIdx.x * 256 + threadIdx.x;
    int row = idx >> 7;
    float l = Lp[row] + Lp[NTOK + row];
    float o = (Op[idx] + Op[(size_t)NTOK * 128 + idx]) * (1.0f / (l * 8192.0f));
    float v = o + R[idx];
    if (applyGelu) v = gelu_f(v);
    bf16 h, lo; split_bf16(v, h, lo);
    Xh[idx] = h; Xl[idx] = lo;
}

// ---------------- local attention -> split bf16 ----------------
__global__ void __launch_bounds__(256) local_attn_kernel(
    const float* __restrict__ Q, const float* __restrict__ K,
    const float* __restrict__ V, const int* __restrict__ nbr,
    const float* __restrict__ R, bf16* __restrict__ Xh, bf16* __restrict__ Xl)
{
    __shared__ float qs[8][128];
    __shared__ float ps[8][8][32];
    __shared__ int   js[8][32];
    int w = threadIdx.x >> 5, lane = threadIdx.x & 31;
    int n = blockIdx.x * 8 + w;

    float4 qv = *(const float4*)&Q[n * 128 + lane * 4];
    *(float4*)&qs[w][lane * 4] = make_float4(qv.x * 0.25f, qv.y * 0.25f, qv.z * 0.25f, qv.w * 0.25f);
    int j = nbr[n * 32 + lane];
    js[w][lane] = j;
    __syncwarp();

    const float* krow = K + (size_t)j * 128;
    float sc[8];
#pragma unroll
    for (int h = 0; h < 8; h++) {
        float4 a0 = *(const float4*)&krow[h * 16 + 0];
        float4 a1 = *(const float4*)&krow[h * 16 + 4];
        float4 a2 = *(const float4*)&krow[h * 16 + 8];
        float4 a3 = *(const float4*)&krow[h * 16 + 12];
        const float* q = &qs[w][h * 16];
        sc[h] = q[0]*a0.x + q[1]*a0.y + q[2]*a0.z + q[3]*a0.w
              + q[4]*a1.x + q[5]*a1.y + q[6]*a1.z + q[7]*a1.w
              + q[8]*a2.x + q[9]*a2.y + q[10]*a2.z + q[11]*a2.w
              + q[12]*a3.x + q[13]*a3.y + q[14]*a3.z + q[15]*a3.w;
    }
#pragma unroll
    for (int h = 0; h < 8; h++) {
        float mx = sc[h];
#pragma unroll
        for (int o = 16; o; o >>= 1) mx = fmaxf(mx, __shfl_xor_sync(0xffffffffu, mx, o));
        float p = __expf(sc[h] - mx);
        float su = p;
#pragma unroll
        for (int o = 16; o; o >>= 1) su += __shfl_xor_sync(0xffffffffu, su, o);
        ps[w][h][lane] = p / su;
    }
    __syncwarp();

    float acc[4] = {0.f, 0.f, 0.f, 0.f};
#pragma unroll 4
    for (int k = 0; k < 32; k++) {
        int jj = js[w][k];
        const float* vrow = V + (size_t)jj * 128;
#pragma unroll
        for (int i = 0; i < 4; i++) {
            int c = lane + 32 * i;
            acc[i] += ps[w][c >> 4][k] * vrow[c];
        }
    }
#pragma unroll
    for (int i = 0; i < 4; i++) {
        int c = lane + 32 * i;
        float v = gelu_f(acc[i] + R[n * 128 + c]);
        bf16 h, lo; split_bf16(v, h, lo);
        Xh[n * 128 + c] = h; Xl[n * 128 + c] = lo;
    }
}

// ---------------- fc2 ----------------
__global__ void __launch_bounds__(256) fc2_kernel(
    const float* __restrict__ H, const float* __restrict__ w,
    const float* __restrict__ b, float* __restrict__ out)
{
    int n = (blockIdx.x * 256 + threadIdx.x) >> 5;
    int lane = threadIdx.x & 31;
    const float4* h4 = (const float4*)(H + (size_t)n * 256);
    const float4* w4 = (const float4*)w;
    float acc = 0.f;
#pragma unroll
    for (int i = 0; i < 2; i++) {
        float4 hv = h4[lane + 32 * i];
        float4 wv = w4[lane + 32 * i];
        acc += hv.x * wv.x + hv.y * wv.y + hv.z * wv.z + hv.w * wv.w;
    }
#pragma unroll
    for (int o = 16; o; o >>= 1) acc += __shfl_xor_sync(0xffffffffu, acc, o);
    if (!lane) out[n] = acc + b[0];
}

// ---------------- host orchestration ----------------
extern "C" void kernel_launch(void* const* d_in, const int* in_sizes, int n_in,
                              void* d_out, int out_size)
{
    (void)in_sizes; (void)n_in; (void)out_size;
    const float* x    = (const float*)d_in[0];
    const float* fc0w = (const float*)d_in[1];
    const float* fc0b = (const float*)d_in[2];
    const float* fc1b = (const float*)d_in[28];
    const float* fc2w = (const float*)d_in[29];
    const float* fc2b = (const float*)d_in[30];
    const int*   nbr  = (const int*)d_in[31];

    float *Qb, *Kb, *Vb, *Rb, *H, *L;
    bf16 *Xh, *Xl, *Wth, *Wtl;
    cudaGetSymbolAddress((void**)&Qb, g_Qb);
    cudaGetSymbolAddress((void**)&Kb, g_Kb);
    cudaGetSymbolAddress((void**)&Vb, g_Vb);
    cudaGetSymbolAddress((void**)&Rb, g_Rb);
    cudaGetSymbolAddress((void**)&H,  g_H);
    cudaGetSymbolAddress((void**)&L,  g_L);
    cudaGetSymbolAddress((void**)&Xh, g_Xh);
    cudaGetSymbolAddress((void**)&Xl, g_Xl);
    cudaGetSymbolAddress((void**)&Wth, g_Wth);
    cudaGetSymbolAddress((void**)&Wtl, g_Wtl);

    cudaFuncSetAttribute(flash_mma_kernel, cudaFuncAttributeMaxDynamicSharedMemorySize, FK_SMEM);
    cudaFuncSetAttribute((const void*)batched_gemm_kernel<1,0>, cudaFuncAttributeMaxDynamicSharedMemorySize, GEMM_SMEM_1);
    cudaFuncSetAttribute((const void*)batched_gemm_kernel<3,1>, cudaFuncAttributeMaxDynamicSharedMemorySize, GEMM_SMEM_3);

    static cudaStream_t sSide = nullptr;
    static cudaEvent_t evForkW, evWconv, evFork0, evW0, evFork2, evW2;
    if (!sSide) {
        cudaStreamCreateWithFlags(&sSide, cudaStreamNonBlocking);
        cudaEventCreateWithFlags(&evForkW, cudaEventDisableTiming);
        cudaEventCreateWithFlags(&evWconv, cudaEventDisableTiming);
        cudaEventCreateWithFlags(&evFork0, cudaEventDisableTiming);
        cudaEventCreateWithFlags(&evW0,    cudaEventDisableTiming);
        cudaEventCreateWithFlags(&evFork2, cudaEventDisableTiming);
        cudaEventCreateWithFlags(&evW2,    cudaEventDisableTiming);
    }

    // fork first, then wconv on side concurrent with fc0 on main
    cudaEventRecord(evForkW, 0);
    cudaStreamWaitEvent(sSide, evForkW, 0);
    {
        WPtrs p;
        for (int i = 0; i < 3; i++) {
            p.w[4 * i + 0] = (const float*)d_in[3 + 8 * i];
            p.w[4 * i + 1] = (const float*)d_in[5 + 8 * i];
            p.w[4 * i + 2] = (const float*)d_in[7 + 8 * i];
            p.w[4 * i + 3] = (const float*)d_in[9 + 8 * i];
            p.cols[4 * i + 0] = p.cols[4 * i + 1] = p.cols[4 * i + 2] = p.cols[4 * i + 3] = 128;
        }
        p.w[12] = (const float*)d_in[27];
        p.cols[12] = 256;
        wconv_kernel<<<dim3(8, 4, 13), 256, 0, sSide>>>(p, Wth, Wtl);
        cudaEventRecord(evWconv, sSide);
    }
    const size_t SLOT = 256 * 128;

    fc0_kernel<<<NTOK * 128 / 256, 256>>>(x, fc0w, fc0b, Xh, Xl);
    cudaStreamWaitEvent(0, evWconv, 0);

    dim3 gQKV(NTOK / 64, 3), gL1(NTOK / 128, 4), gW(NTOK / 128, 1), gFC1(NTOK / 128, 2);

    // ---- layer 0 (global, gelu): QKV 64-row 1-term; W 128-row 3-term on side ----
    {
        cudaEventRecord(evFork0, 0);
        cudaStreamWaitEvent(sSide, evFork0, 0);
        GBatch w;
        w.s[0] = { Wth + 3*SLOT, Wtl + 3*SLOT, (const float*)d_in[10], Rb, 128, 0 };
        batched_gemm_kernel<3,1><<<gW, 256, GEMM_SMEM_3, sSide>>>(Xh, Xl, w);
        cudaEventRecord(evW0, sSide);

        GBatch qkv;
        qkv.s[0] = { Wth + 0*SLOT, Wtl + 0*SLOT, (const float*)d_in[4], Qb, 128, 2 };
        qkv.s[1] = { Wth + 1*SLOT, Wtl + 1*SLOT, (const float*)d_in[6], Kb, 128, 2 };
        qkv.s[2] = { Wth + 2*SLOT, Wtl + 2*SLOT, (const float*)d_in[8], Vb, 128, 3 };
        batched_gemm_kernel<1,0><<<gQKV, 256, GEMM_SMEM_1>>>(Xh, Xl, qkv);
        flash_mma_kernel<<<128, 256, FK_SMEM>>>((const bf16*)Qb, (const bf16*)Kb, (const bf16*)Vb, H, L);
        cudaStreamWaitEvent(0, evW0, 0);
        combine_kernel<<<NTOK * 128 / 256, 256>>>(H, L, Rb, Xh, Xl, 1);
    }

    // ---- layer 1 (local, gelu): all 3-term 128-row, one batched launch ----
    {
        GBatch a;
        a.s[0] = { Wth + 4*SLOT, Wtl + 4*SLOT, (const float*)d_in[12], Qb, 128, 0 };
        a.s[1] = { Wth + 5*SLOT, Wtl + 5*SLOT, (const float*)d_in[14], Kb, 128, 0 };
        a.s[2] = { Wth + 6*SLOT, Wtl + 6*SLOT, (const float*)d_in[16], Vb, 128, 0 };
        a.s[3] = { Wth + 7*SLOT, Wtl + 7*SLOT, (const float*)d_in[18], Rb, 128, 0 };
        batched_gemm_kernel<3,1><<<gL1, 256, GEMM_SMEM_3>>>(Xh, Xl, a);
        local_attn_kernel<<<NTOK / 8, 256>>>(Qb, Kb, Vb, nbr, Rb, Xh, Xl);
    }

    // ---- layer 2 (global, no act): same pattern ----
    {
        cudaEventRecord(evFork2, 0);
        cudaStreamWaitEvent(sSide, evFork2, 0);
        GBatch w;
        w.s[0] = { Wth + 11*SLOT, Wtl + 11*SLOT, (const float*)d_in[26], Rb, 128, 0 };
        batched_gemm_kernel<3,1><<<gW, 256, GEMM_SMEM_3, sSide>>>(Xh, Xl, w);
        cudaEventRecord(evW2, sSide);

        GBatch qkv;
        qkv.s[0] = { Wth + 8*SLOT,  Wtl + 8*SLOT,  (const float*)d_in[20], Qb, 128, 2 };
        qkv.s[1] = { Wth + 9*SLOT,  Wtl + 9*SLOT,  (const float*)d_in[22], Kb, 128, 2 };
        qkv.s[2] = { Wth + 10*SLOT, Wtl + 10*SLOT, (const float*)d_in[24], Vb, 128, 3 };
        batched_gemm_kernel<1,0><<<gQKV, 256, GEMM_SMEM_1>>>(Xh, Xl, qkv);
        flash_mma_kernel<<<128, 256, FK_SMEM>>>((const bf16*)Qb, (const bf16*)Kb, (const bf16*)Vb, H, L);
        cudaStreamWaitEvent(0, evW2, 0);
        combine_kernel<<<NTOK * 128 / 256, 256>>>(H, L, Rb, Xh, Xl, 0);
    }

    // fc1 (3-term 128-row, gelu) + fc2
    {
        GBatch a;
        a.s[0] = { Wth + 12*SLOT,             Wtl + 12*SLOT,             fc1b,       H,       256, 1 };
        a.s[1] = { Wth + 12*SLOT + 128 * 128, Wtl + 12*SLOT + 128 * 128, fc1b + 128, H + 128, 256, 1 };
        batched_gemm_kernel<3,1><<<gFC1, 256, GEMM_SMEM_3>>>(Xh, Xl, a);
    }
    fc2_kernel<<<NTOK * 32 / 256, 256>>>(H, fc2w, fc2b, (float*)d_out);
}

// round 17
// speedup vs baseline: 1.1534x; 1.0219x over previous
#include <cuda_runtime.h>
#include <cuda_bf16.h>
#include <math.h>
#include <cstdint>

#define NTOK 8192
typedef unsigned long long u64;
typedef __nv_bfloat16 bf16;

// ---------------- scratch ----------------
__device__ float g_Qb[NTOK * 128];
__device__ float g_Kb[NTOK * 128];
__device__ float g_Vb[NTOK * 128];
__device__ float g_Rb[NTOK * 128];
__device__ float g_H[NTOK * 256];      // reused as O partials (2 x 1M floats)
__device__ float g_L[2 * NTOK];
__device__ bf16  g_Xh[NTOK * 128];
__device__ bf16  g_Xl[NTOK * 128];
__device__ bf16  g_Wth[13 * 256 * 128];
__device__ bf16  g_Wtl[13 * 256 * 128];

// ---------------- helpers ----------------
__device__ __forceinline__ float gelu_f(float x) {
    return 0.5f * x * (1.0f + erff(x * 0.7071067811865476f));
}
__device__ __forceinline__ uint32_t pack_bf16(float lo, float hi) {
    uint32_t r; asm("cvt.rn.bf16x2.f32 %0, %1, %2;" : "=r"(r) : "f"(hi), "f"(lo)); return r;
}
__device__ __forceinline__ uint32_t smem_u32(const void* p) {
    uint32_t a; asm("{ .reg .u64 t; cvta.to.shared.u64 t, %1; cvt.u32.u64 %0, t; }" : "=r"(a) : "l"(p));
    return a;
}
__device__ __forceinline__ void split_bf16(float v, bf16& h, bf16& l) {
    h = __float2bfloat16(v);
    l = __float2bfloat16(v - __bfloat162float(h));
}
__device__ __forceinline__ float ex2(float x) {
    float r; asm("ex2.approx.ftz.f32 %0, %1;" : "=f"(r) : "f"(x)); return r;
}

// ---------------- mma.sync / ldmatrix / cp.async primitives ----------------
__device__ __forceinline__ void mma16816(float* c, const uint32_t* a, uint32_t b0, uint32_t b1) {
    asm volatile("mma.sync.aligned.m16n8k16.row.col.f32.bf16.bf16.f32 "
        "{%0,%1,%2,%3}, {%4,%5,%6,%7}, {%8,%9}, {%0,%1,%2,%3};"
        : "+f"(c[0]), "+f"(c[1]), "+f"(c[2]), "+f"(c[3])
        : "r"(a[0]), "r"(a[1]), "r"(a[2]), "r"(a[3]), "r"(b0), "r"(b1));
}
__device__ __forceinline__ void ldsm4(uint32_t* r, uint32_t addr) {
    asm volatile("ldmatrix.sync.aligned.m8n8.x4.shared.b16 {%0,%1,%2,%3}, [%4];"
        : "=r"(r[0]), "=r"(r[1]), "=r"(r[2]), "=r"(r[3]) : "r"(addr));
}
__device__ __forceinline__ void cp16(uint32_t sdst, const void* gsrc) {
    asm volatile("cp.async.cg.shared.global [%0], [%1], 16;" :: "r"(sdst), "l"(gsrc));
}
#define CP_COMMIT() asm volatile("cp.async.commit_group;" ::: "memory")
#define CP_WAIT1()  asm volatile("cp.async.wait_group 1;" ::: "memory")
#define CP_WAIT0()  asm volatile("cp.async.wait_group 0;" ::: "memory")

// tile geometry: 128 rows x 128 bf16, rows padded to 272 bytes
#define TROW 272
#define TILE_BYTES (128 * TROW)

__device__ __forceinline__ void copy_tile_async(char* dst, const bf16* __restrict__ src,
                                                int rstride, int tid) {
    uint32_t d = smem_u32(dst);
#pragma unroll
    for (int rep = 0; rep < 8; rep++) {
        int chunk = rep * 256 + tid;       // 2048 chunks of 16B
        int r = chunk >> 4, c = chunk & 15;
        cp16(d + r * TROW + c * 16, src + (size_t)r * rstride + c * 8);
    }
}
__device__ __forceinline__ void copy_x64_async(char* dst, const bf16* __restrict__ src, int tid) {
    uint32_t d = smem_u32(dst);
#pragma unroll
    for (int rep = 0; rep < 4; rep++) {
        int chunk = rep * 256 + tid;       // 1024 chunks (64 rows)
        int r = chunk >> 4, c = chunk & 15;
        cp16(d + r * TROW + c * 16, src + (size_t)r * 128 + c * 8);
    }
}

// ---------------- weight transpose + bf16 split (once per launch) ----------------
struct WPtrs { const float* w[13]; int cols[13]; };

__global__ void __launch_bounds__(256) wconv_kernel(WPtrs p, bf16* Wth, bf16* Wtl) {
    int m = blockIdx.z;
    int colsM = p.cols[m];
    int c0 = blockIdx.x * 32, k0 = blockIdx.y * 32;
    if (c0 >= colsM) return;
    __shared__ float t[32][33];
    int tx = threadIdx.x & 31, ty = threadIdx.x >> 5;
    const float* W = p.w[m];
#pragma unroll
    for (int i = 0; i < 4; i++) {
        int k = k0 + ty + 8 * i;
        t[ty + 8 * i][tx] = W[(size_t)k * colsM + c0 + tx];
    }
    __syncthreads();
    size_t slot = (size_t)m * 256 * 128;
#pragma unroll
    for (int i = 0; i < 4; i++) {
        int col = c0 + ty + 8 * i;
        int kk = k0 + tx;
        float v = t[tx][ty + 8 * i];
        bf16 h, l; split_bf16(v, h, l);
        Wth[slot + (size_t)col * 128 + kk] = h;
        Wtl[slot + (size_t)col * 128 + kk] = l;
    }
}

// ---------------- fc0 -> split bf16 ----------------
__global__ void __launch_bounds__(256) fc0_kernel(
    const float* __restrict__ x, const float* __restrict__ w,
    const float* __restrict__ b, bf16* __restrict__ Xh, bf16* __restrict__ Xl)
{
    int idx = blockIdx.x * 256 + threadIdx.x;
    int n = idx >> 7, c = idx & 127;
    float x0 = x[n * 3 + 0], x1 = x[n * 3 + 1], x2 = x[n * 3 + 2];
    float v = fmaf(x0, w[c], fmaf(x1, w[128 + c], fmaf(x2, w[256 + c], b[c])));
    bf16 h, l; split_bf16(v, h, l);
    Xh[idx] = h; Xl[idx] = l;
}

// ---------------- batched tensor-core GEMM ----------------
// R128=1: 128 rows per CTA (two 64-row halves). R128=0: 64 rows per CTA.
struct GSlot { const bf16* Wh; const bf16* Wl; const float* bias; void* out; int M; int mode; };
struct GBatch { GSlot s[4]; };

#define GEMM_SMEM_1 (64 * TROW + 128 * TROW)
#define GEMM_SMEM_3 (2 * (64 * TROW + 128 * TROW))

template<int TERMS, int R128>
__global__ void __launch_bounds__(256) batched_gemm_kernel(
    const bf16* __restrict__ Xh, const bf16* __restrict__ Xl, GBatch args)
{
    extern __shared__ char sm[];
    char* sXh = sm;
    char* sWh = sm + 64 * TROW;
    char* sXl = sWh + 128 * TROW;
    char* sWl = sXl + 64 * TROW;

    GSlot sl = args.s[blockIdx.y];
    int tid = threadIdx.x, wid = tid >> 5, lane = tid & 31;
    int row_base = blockIdx.x * (R128 ? 128 : 64);

    copy_x64_async(sXh, Xh + (size_t)row_base * 128, tid);
    copy_tile_async(sWh, sl.Wh, 128, tid);
    if (TERMS == 3) {
        copy_x64_async(sXl, Xl + (size_t)row_base * 128, tid);
        copy_tile_async(sWl, sl.Wl, 128, tid);
    }
    CP_COMMIT();
    CP_WAIT0();
    __syncthreads();

    int rowBlk = wid & 3, colHalf = wid >> 2;
    uint32_t tb_off = (lane & 7) * TROW + (lane >> 3) * 16;
    uint32_t whB = smem_u32(sWh), wlB = smem_u32(sWl);
    uint32_t xfrag = (uint32_t)(rowBlk * 16 + (lane & 15)) * TROW + (uint32_t)(lane >> 4) * 16;
    int g = lane >> 2, tig = lane & 3;
    int M = sl.M, mode = sl.mode;

#pragma unroll
    for (int h2 = 0; h2 < (R128 ? 2 : 1); h2++) {
        uint32_t ah[8][4], al[8][4];
        {
            uint32_t qb_ = smem_u32(sXh) + xfrag;
#pragma unroll
            for (int kb = 0; kb < 8; kb++) ldsm4(ah[kb], qb_ + kb * 32);
            if (TERMS == 3) {
                uint32_t ql_ = smem_u32(sXl) + xfrag;
#pragma unroll
                for (int kb = 0; kb < 8; kb++) ldsm4(al[kb], ql_ + kb * 32);
            }
        }
        if (R128) {
            __syncthreads();
            if (h2 == 0) {
                copy_x64_async(sXh, Xh + (size_t)(row_base + 64) * 128, tid);
                if (TERMS == 3) copy_x64_async(sXl, Xl + (size_t)(row_base + 64) * 128, tid);
                CP_COMMIT();
            }
        }

        float acc[8][4];
#pragma unroll
        for (int nb = 0; nb < 8; nb++)
#pragma unroll
            for (int j = 0; j < 4; j++) acc[nb][j] = 0.f;

#pragma unroll
        for (int nb = 0; nb < 8; nb++) {
            uint32_t kf[16];
            uint32_t a = whB + (colHalf * 8 + nb) * (8 * TROW) + tb_off;
#pragma unroll
            for (int q = 0; q < 4; q++) ldsm4(kf + 4 * q, a + q * 64);
#pragma unroll
            for (int s = 0; s < 8; s++) mma16816(acc[nb], ah[s], kf[2 * s], kf[2 * s + 1]);
            if (TERMS == 3) {
#pragma unroll
                for (int s = 0; s < 8; s++) mma16816(acc[nb], al[s], kf[2 * s], kf[2 * s + 1]);
                uint32_t kl[16];
                uint32_t a2 = wlB + (colHalf * 8 + nb) * (8 * TROW) + tb_off;
#pragma unroll
                for (int q = 0; q < 4; q++) ldsm4(kl + 4 * q, a2 + q * 64);
#pragma unroll
                for (int s = 0; s < 8; s++) mma16816(acc[nb], ah[s], kl[2 * s], kl[2 * s + 1]);
            }
        }

        int r0 = row_base + h2 * 64 + rowBlk * 16 + g, r1 = r0 + 8;
#pragma unroll
        for (int nb = 0; nb < 8; nb++) {
            int col = colHalf * 64 + nb * 8 + tig * 2;
            float b0 = sl.bias[col], b1 = sl.bias[col + 1];
            float v00 = acc[nb][0] + b0, v01 = acc[nb][1] + b1;
            float v10 = acc[nb][2] + b0, v11 = acc[nb][3] + b1;
            if (mode == 1) { v00 = gelu_f(v00); v01 = gelu_f(v01); v10 = gelu_f(v10); v11 = gelu_f(v11); }
            if (mode <= 1) {
                float* C = (float*)sl.out;
                *(float2*)&C[(size_t)r0 * M + col] = make_float2(v00, v01);
                *(float2*)&C[(size_t)r1 * M + col] = make_float2(v10, v11);
            } else if (mode == 2) {
                bf16* Cb = (bf16*)sl.out;
                *(uint32_t*)&Cb[(size_t)r0 * M + col] = pack_bf16(v00, v01);
                *(uint32_t*)&Cb[(size_t)r1 * M + col] = pack_bf16(v10, v11);
            } else {
                bf16* Cb = (bf16*)sl.out;
                Cb[(size_t)col * NTOK + r0]       = __float2bfloat16(v00);
                Cb[(size_t)(col + 1) * NTOK + r0] = __float2bfloat16(v01);
                Cb[(size_t)col * NTOK + r1]       = __float2bfloat16(v10);
                Cb[(size_t)(col + 1) * NTOK + r1] = __float2bfloat16(v11);
            }
        }

        if (R128 && h2 == 0) {
            CP_WAIT0();
            __syncthreads();
        }
    }
}

// ---------------- flash attention: 3-deep K/V rings, ONE sync per iteration ----------------
// smem: Q + 3K + 2V tiles; V slot 2 aliases the Q tile (dead after fragment load).
#define FK_SMEM (6 * TILE_BYTES)   // 208896
#define SC2F (0.088388347761972741f * 1.4426950408889634f)   // 1/sqrt(128)*log2(e)

__global__ void __launch_bounds__(256) flash_mma_kernel(
    const bf16* __restrict__ Q, const bf16* __restrict__ K,
    const bf16* __restrict__ Vt, float* __restrict__ Opart, float* __restrict__ Lpart)
{
    extern __shared__ char sm[];
    char* sQ = sm;
    char* sK[3] = { sm + TILE_BYTES, sm + 2 * TILE_BYTES, sm + 3 * TILE_BYTES };
    char* sV[3] = { sm + 4 * TILE_BYTES, sm + 5 * TILE_BYTES, sQ };   // slot 2 = Q tile

    int tid = threadIdx.x, wid = tid >> 5, lane = tid & 31;
    int qb = blockIdx.x >> 1, part = blockIdx.x & 1;
    int key0 = part * 4096;

    copy_tile_async(sQ,    Q  + (size_t)(qb * 128) * 128, 128, tid);
    copy_tile_async(sK[0], K  + (size_t)key0 * 128,       128, tid);
    copy_tile_async(sV[0], Vt + key0,                    NTOK, tid);
    CP_COMMIT();
    copy_tile_async(sK[1], K  + (size_t)(key0 + 128) * 128, 128, tid);
    copy_tile_async(sV[1], Vt + key0 + 128,                NTOK, tid);
    CP_COMMIT();

    CP_WAIT1();          // G0 done: Q, K0, V0 resident
    __syncthreads();

    uint32_t qf[8][4];
    {
        uint32_t qbase = smem_u32(sQ) + (wid * 16 + (lane & 15)) * TROW + (lane >> 4) * 16;
#pragma unroll
        for (int kb = 0; kb < 8; kb++) ldsm4(qf[kb], qbase + kb * 32);
    }

    float oacc[16][4];
#pragma unroll
    for (int nb = 0; nb < 16; nb++)
#pragma unroll
        for (int j = 0; j < 4; j++) oacc[nb][j] = 0.f;
    float lacc0 = 0.f, lacc1 = 0.f;

    uint32_t tb_off = (lane & 7) * TROW + (lane >> 3) * 16;

#define FLASH_BODY(kB_, vB_)                                                        \
    {                                                                               \
        uint32_t kB = (kB_);                                                        \
        uint32_t vB = (vB_);                                                        \
        uint32_t pf[8][4];                                                          \
        _Pragma("unroll")                                                           \
        for (int j = 0; j < 8; j++) {                                               \
            float s0[4] = {0.f, 0.f, 0.f, 0.f};                                     \
            float s1[4] = {0.f, 0.f, 0.f, 0.f};                                     \
            uint32_t kf[16];                                                        \
            uint32_t a0 = kB + (2 * j) * (8 * TROW) + tb_off;                       \
            _Pragma("unroll")                                                       \
            for (int q = 0; q < 4; q++) ldsm4(kf + 4 * q, a0 + q * 64);             \
            _Pragma("unroll")                                                       \
            for (int s = 0; s < 8; s++) mma16816(s0, qf[s], kf[2*s], kf[2*s+1]);    \
            uint32_t a1 = kB + (2 * j + 1) * (8 * TROW) + tb_off;                   \
            _Pragma("unroll")                                                       \
            for (int q = 0; q < 4; q++) ldsm4(kf + 4 * q, a1 + q * 64);             \
            _Pragma("unroll")                                                       \
            for (int s = 0; s < 8; s++) mma16816(s1, qf[s], kf[2*s], kf[2*s+1]);    \
            float e00 = ex2(s0[0] * SC2F), e01 = ex2(s0[1] * SC2F);                 \
            float e02 = ex2(s0[2] * SC2F), e03 = ex2(s0[3] * SC2F);                 \
            float e10 = ex2(s1[0] * SC2F), e11 = ex2(s1[1] * SC2F);                 \
            float e12 = ex2(s1[2] * SC2F), e13 = ex2(s1[3] * SC2F);                 \
            lacc0 += (e00 + e01) + (e10 + e11);                                     \
            lacc1 += (e02 + e03) + (e12 + e13);                                     \
            pf[j][0] = pack_bf16(e00, e01);                                         \
            pf[j][1] = pack_bf16(e02, e03);                                         \
            pf[j][2] = pack_bf16(e10, e11);                                         \
            pf[j][3] = pack_bf16(e12, e13);                                         \
        }                                                                           \
        _Pragma("unroll")                                                           \
        for (int nb = 0; nb < 16; nb++) {                                           \
            uint32_t vf[16];                                                        \
            uint32_t a = vB + nb * (8 * TROW) + tb_off;                             \
            _Pragma("unroll")                                                       \
            for (int q = 0; q < 4; q++) ldsm4(vf + 4 * q, a + q * 64);              \
            _Pragma("unroll")                                                       \
            for (int s = 0; s < 8; s++) mma16816(oacc[nb], pf[s], vf[2*s], vf[2*s+1]); \
        }                                                                           \
    }

    // ---- iter 0 (peeled, classic 2-sync structure protects Q fragment reads) ----
    FLASH_BODY(smem_u32(sK[0]), smem_u32(sV[0]));
    __syncthreads();                       // everyone done reading Q tile + tile 0
    copy_tile_async(sK[2], K  + (size_t)(key0 + 2 * 128) * 128, 128, tid);
    copy_tile_async(sV[2], Vt + key0 + 2 * 128, NTOK, tid);    // writes sQ slot
    CP_COMMIT();                           // G2

    // ---- iters 1..31: ONE sync per iteration ----
    for (int i = 1; i < 32; i++) {
        CP_WAIT1();                        // tile i resident
        __syncthreads();                   // all warps past iter i-1 -> slot (i+2)%3 free
        if (i + 2 < 32) {
            copy_tile_async(sK[(i + 2) % 3], K  + (size_t)(key0 + (i + 2) * 128) * 128, 128, tid);
            copy_tile_async(sV[(i + 2) % 3], Vt + key0 + (i + 2) * 128, NTOK, tid);
        }
        CP_COMMIT();                       // uniform group ledger
        FLASH_BODY(smem_u32(sK[i % 3]), smem_u32(sV[i % 3]));
    }
#undef FLASH_BODY

    int g = lane >> 2, tig = lane & 3;
    int row0 = qb * 128 + wid * 16 + g;
    float* o0 = Opart + ((size_t)part * NTOK + row0) * 128;
    float* o1 = o0 + 8 * 128;
#pragma unroll
    for (int nb = 0; nb < 16; nb++) {
        *(float2*)&o0[nb * 8 + tig * 2] = make_float2(oacc[nb][0], oacc[nb][1]);
        *(float2*)&o1[nb * 8 + tig * 2] = make_float2(oacc[nb][2], oacc[nb][3]);
    }
    lacc0 += __shfl_xor_sync(0xffffffffu, lacc0, 1);
    lacc0 += __shfl_xor_sync(0xffffffffu, lacc0, 2);
    lacc1 += __shfl_xor_sync(0xffffffffu, lacc1, 1);
    lacc1 += __shfl_xor_sync(0xffffffffu, lacc1, 2);
    if (tig == 0) {
        Lpart[part * NTOK + row0]     = lacc0;
        Lpart[part * NTOK + row0 + 8] = lacc1;
    }
}

// ---------------- combine split-2 partials + residual (+gelu) -> split bf16 ----------------
__global__ void __launch_bounds__(256) combine_kernel(
    const float* __restrict__ Op, const float* __restrict__ Lp,
    const float* __restrict__ R, bf16* __restrict__ Xh, bf16* __restrict__ Xl, int applyGelu)
{
    int idx = blockIdx.x * 256 + threadIdx.x;
    int row = idx >> 7;
    float l = Lp[row] + Lp[NTOK + row];
    float o = (Op[idx] + Op[(size_t)NTOK * 128 + idx]) * (1.0f / (l * 8192.0f));
    float v = o + R[idx];
    if (applyGelu) v = gelu_f(v);
    bf16 h, lo; split_bf16(v, h, lo);
    Xh[idx] = h; Xl[idx] = lo;
}

// ---------------- local attention -> split bf16 ----------------
__global__ void __launch_bounds__(256) local_attn_kernel(
    const float* __restrict__ Q, const float* __restrict__ K,
    const float* __restrict__ V, const int* __restrict__ nbr,
    const float* __restrict__ R, bf16* __restrict__ Xh, bf16* __restrict__ Xl)
{
    __shared__ float qs[8][128];
    __shared__ float ps[8][8][32];
    __shared__ int   js[8][32];
    int w = threadIdx.x >> 5, lane = threadIdx.x & 31;
    int n = blockIdx.x * 8 + w;

    float4 qv = *(const float4*)&Q[n * 128 + lane * 4];
    *(float4*)&qs[w][lane * 4] = make_float4(qv.x * 0.25f, qv.y * 0.25f, qv.z * 0.25f, qv.w * 0.25f);
    int j = nbr[n * 32 + lane];
    js[w][lane] = j;
    __syncwarp();

    const float* krow = K + (size_t)j * 128;
    float sc[8];
#pragma unroll
    for (int h = 0; h < 8; h++) {
        float4 a0 = *(const float4*)&krow[h * 16 + 0];
        float4 a1 = *(const float4*)&krow[h * 16 + 4];
        float4 a2 = *(const float4*)&krow[h * 16 + 8];
        float4 a3 = *(const float4*)&krow[h * 16 + 12];
        const float* q = &qs[w][h * 16];
        sc[h] = q[0]*a0.x + q[1]*a0.y + q[2]*a0.z + q[3]*a0.w
              + q[4]*a1.x + q[5]*a1.y + q[6]*a1.z + q[7]*a1.w
              + q[8]*a2.x + q[9]*a2.y + q[10]*a2.z + q[11]*a2.w
              + q[12]*a3.x + q[13]*a3.y + q[14]*a3.z + q[15]*a3.w;
    }
#pragma unroll
    for (int h = 0; h < 8; h++) {
        float mx = sc[h];
#pragma unroll
        for (int o = 16; o; o >>= 1) mx = fmaxf(mx, __shfl_xor_sync(0xffffffffu, mx, o));
        float p = __expf(sc[h] - mx);
        float su = p;
#pragma unroll
        for (int o = 16; o; o >>= 1) su += __shfl_xor_sync(0xffffffffu, su, o);
        ps[w][h][lane] = p / su;
    }
    __syncwarp();

    float acc[4] = {0.f, 0.f, 0.f, 0.f};
#pragma unroll 4
    for (int k = 0; k < 32; k++) {
        int jj = js[w][k];
        const float* vrow = V + (size_t)jj * 128;
#pragma unroll
        for (int i = 0; i < 4; i++) {
            int c = lane + 32 * i;
            acc[i] += ps[w][c >> 4][k] * vrow[c];
        }
    }
#pragma unroll
    for (int i = 0; i < 4; i++) {
        int c = lane + 32 * i;
        float v = gelu_f(acc[i] + R[n * 128 + c]);
        bf16 h, lo; split_bf16(v, h, lo);
        Xh[n * 128 + c] = h; Xl[n * 128 + c] = lo;
    }
}

// ---------------- fc2 ----------------
__global__ void __launch_bounds__(256) fc2_kernel(
    const float* __restrict__ H, const float* __restrict__ w,
    const float* __restrict__ b, float* __restrict__ out)
{
    int n = (blockIdx.x * 256 + threadIdx.x) >> 5;
    int lane = threadIdx.x & 31;
    const float4* h4 = (const float4*)(H + (size_t)n * 256);
    const float4* w4 = (const float4*)w;
    float acc = 0.f;
#pragma unroll
    for (int i = 0; i < 2; i++) {
        float4 hv = h4[lane + 32 * i];
        float4 wv = w4[lane + 32 * i];
        acc += hv.x * wv.x + hv.y * wv.y + hv.z * wv.z + hv.w * wv.w;
    }
#pragma unroll
    for (int o = 16; o; o >>= 1) acc += __shfl_xor_sync(0xffffffffu, acc, o);
    if (!lane) out[n] = acc + b[0];
}

// ---------------- host orchestration ----------------
extern "C" void kernel_launch(void* const* d_in, const int* in_sizes, int n_in,
                              void* d_out, int out_size)
{
    (void)in_sizes; (void)n_in; (void)out_size;
    const float* x    = (const float*)d_in[0];
    const float* fc0w = (const float*)d_in[1];
    const float* fc0b = (const float*)d_in[2];
    const float* fc1b = (const float*)d_in[28];
    const float* fc2w = (const float*)d_in[29];
    const float* fc2b = (const float*)d_in[30];
    const int*   nbr  = (const int*)d_in[31];

    float *Qb, *Kb, *Vb, *Rb, *H, *L;
    bf16 *Xh, *Xl, *Wth, *Wtl;
    cudaGetSymbolAddress((void**)&Qb, g_Qb);
    cudaGetSymbolAddress((void**)&Kb, g_Kb);
    cudaGetSymbolAddress((void**)&Vb, g_Vb);
    cudaGetSymbolAddress((void**)&Rb, g_Rb);
    cudaGetSymbolAddress((void**)&H,  g_H);
    cudaGetSymbolAddress((void**)&L,  g_L);
    cudaGetSymbolAddress((void**)&Xh, g_Xh);
    cudaGetSymbolAddress((void**)&Xl, g_Xl);
    cudaGetSymbolAddress((void**)&Wth, g_Wth);
    cudaGetSymbolAddress((void**)&Wtl, g_Wtl);

    cudaFuncSetAttribute(flash_mma_kernel, cudaFuncAttributeMaxDynamicSharedMemorySize, FK_SMEM);
    cudaFuncSetAttribute((const void*)batched_gemm_kernel<1,0>, cudaFuncAttributeMaxDynamicSharedMemorySize, GEMM_SMEM_1);
    cudaFuncSetAttribute((const void*)batched_gemm_kernel<3,1>, cudaFuncAttributeMaxDynamicSharedMemorySize, GEMM_SMEM_3);

    static cudaStream_t sSide = nullptr;
    static cudaEvent_t evForkW, evWconv, evFork0, evW0, evFork2, evW2;
    if (!sSide) {
        cudaStreamCreateWithFlags(&sSide, cudaStreamNonBlocking);
        cudaEventCreateWithFlags(&evForkW, cudaEventDisableTiming);
        cudaEventCreateWithFlags(&evWconv, cudaEventDisableTiming);
        cudaEventCreateWithFlags(&evFork0, cudaEventDisableTiming);
        cudaEventCreateWithFlags(&evW0,    cudaEventDisableTiming);
        cudaEventCreateWithFlags(&evFork2, cudaEventDisableTiming);
        cudaEventCreateWithFlags(&evW2,    cudaEventDisableTiming);
    }

    // fork first, then wconv on side concurrent with fc0 on main
    cudaEventRecord(evForkW, 0);
    cudaStreamWaitEvent(sSide, evForkW, 0);
    {
        WPtrs p;
        for (int i = 0; i < 3; i++) {
            p.w[4 * i + 0] = (const float*)d_in[3 + 8 * i];
            p.w[4 * i + 1] = (const float*)d_in[5 + 8 * i];
            p.w[4 * i + 2] = (const float*)d_in[7 + 8 * i];
            p.w[4 * i + 3] = (const float*)d_in[9 + 8 * i];
            p.cols[4 * i + 0] = p.cols[4 * i + 1] = p.cols[4 * i + 2] = p.cols[4 * i + 3] = 128;
        }
        p.w[12] = (const float*)d_in[27];
        p.cols[12] = 256;
        wconv_kernel<<<dim3(8, 4, 13), 256, 0, sSide>>>(p, Wth, Wtl);
        cudaEventRecord(evWconv, sSide);
    }
    const size_t SLOT = 256 * 128;

    fc0_kernel<<<NTOK * 128 / 256, 256>>>(x, fc0w, fc0b, Xh, Xl);
    cudaStreamWaitEvent(0, evWconv, 0);

    dim3 gQKV(NTOK / 64, 3), gL1(NTOK / 128, 4), gW(NTOK / 128, 1), gFC1(NTOK / 128, 2);

    // ---- layer 0 (global, gelu): QKV 64-row 1-term; W 128-row 3-term on side ----
    {
        cudaEventRecord(evFork0, 0);
        cudaStreamWaitEvent(sSide, evFork0, 0);
        GBatch w;
        w.s[0] = { Wth + 3*SLOT, Wtl + 3*SLOT, (const float*)d_in[10], Rb, 128, 0 };
        batched_gemm_kernel<3,1><<<gW, 256, GEMM_SMEM_3, sSide>>>(Xh, Xl, w);
        cudaEventRecord(evW0, sSide);

        GBatch qkv;
        qkv.s[0] = { Wth + 0*SLOT, Wtl + 0*SLOT, (const float*)d_in[4], Qb, 128, 2 };
        qkv.s[1] = { Wth + 1*SLOT, Wtl + 1*SLOT, (const float*)d_in[6], Kb, 128, 2 };
        qkv.s[2] = { Wth + 2*SLOT, Wtl + 2*SLOT, (const float*)d_in[8], Vb, 128, 3 };
        batched_gemm_kernel<1,0><<<gQKV, 256, GEMM_SMEM_1>>>(Xh, Xl, qkv);
        flash_mma_kernel<<<128, 256, FK_SMEM>>>((const bf16*)Qb, (const bf16*)Kb, (const bf16*)Vb, H, L);
        cudaStreamWaitEvent(0, evW0, 0);
        combine_kernel<<<NTOK * 128 / 256, 256>>>(H, L, Rb, Xh, Xl, 1);
    }

    // ---- layer 1 (local, gelu): all 3-term 128-row, one batched launch ----
    {
        GBatch a;
        a.s[0] = { Wth + 4*SLOT, Wtl + 4*SLOT, (const float*)d_in[12], Qb, 128, 0 };
        a.s[1] = { Wth + 5*SLOT, Wtl + 5*SLOT, (const float*)d_in[14], Kb, 128, 0 };
        a.s[2] = { Wth + 6*SLOT, Wtl + 6*SLOT, (const float*)d_in[16], Vb, 128, 0 };
        a.s[3] = { Wth + 7*SLOT, Wtl + 7*SLOT, (const float*)d_in[18], Rb, 128, 0 };
        batched_gemm_kernel<3,1><<<gL1, 256, GEMM_SMEM_3>>>(Xh, Xl, a);
        local_attn_kernel<<<NTOK / 8, 256>>>(Qb, Kb, Vb, nbr, Rb, Xh, Xl);
    }

    // ---- layer 2 (global, no act): same pattern ----
    {
        cudaEventRecord(evFork2, 0);
        cudaStreamWaitEvent(sSide, evFork2, 0);
        GBatch w;
        w.s[0] = { Wth + 11*SLOT, Wtl + 11*SLOT, (const float*)d_in[26], Rb, 128, 0 };
        batched_gemm_kernel<3,1><<<gW, 256, GEMM_SMEM_3, sSide>>>(Xh, Xl, w);
        cudaEventRecord(evW2, sSide);

        GBatch qkv;
        qkv.s[0] = { Wth + 8*SLOT,  Wtl + 8*SLOT,  (const float*)d_in[20], Qb, 128, 2 };
        qkv.s[1] = { Wth + 9*SLOT,  Wtl + 9*SLOT,  (const float*)d_in[22], Kb, 128, 2 };
        qkv.s[2] = { Wth + 10*SLOT, Wtl + 10*SLOT, (const float*)d_in[24], Vb, 128, 3 };
        batched_gemm_kernel<1,0><<<gQKV, 256, GEMM_SMEM_1>>>(Xh, Xl, qkv);
        flash_mma_kernel<<<128, 256, FK_SMEM>>>((const bf16*)Qb, (const bf16*)Kb, (const bf16*)Vb, H, L);
        cudaStreamWaitEvent(0, evW2, 0);
        combine_kernel<<<NTOK * 128 / 256, 256>>>(H, L, Rb, Xh, Xl, 0);
    }

    // fc1 (3-term 128-row, gelu) + fc2
    {
        GBatch a;
        a.s[0] = { Wth + 12*SLOT,             Wtl + 12*SLOT,             fc1b,       H,       256, 1 };
        a.s[1] = { Wth + 12*SLOT + 128 * 128, Wtl + 12*SLOT + 128 * 128, fc1b + 128, H + 128, 256, 1 };
        batched_gemm_kernel<3,1><<<gFC1, 256, GEMM_SMEM_3>>>(Xh, Xl, a);
    }
    fc2_kernel<<<NTOK * 32 / 256, 256>>>(H, fc2w, fc2b, (float*)d_out);
}